// round 1
// baseline (speedup 1.0000x reference)
#include <cuda_runtime.h>
#include <cuda_bf16.h>

#define D 128            // D_IN == D_OUT == 128
#define MAX_N 100000
#define GEMM_ROWS 32     // rows of x per block
#define EPB 256          // edges per block in scatter
#define CHAINS 4         // chains per block (each 32 lanes, EPB/CHAINS edges)

// Scratch for support = x@W + b  (51.2 MB)
__device__ float g_support[MAX_N * D];

// ---------------------------------------------------------------------------
// Kernel 1: support[n][d] = sum_k x[n][k] * W[k][d] + b[d]
// Block: 256 threads = (32 float4-col-groups) x (8 warps). Each warp handles
// 4 rows; each thread accumulates 4 rows x 4 cols. W (64KB) + x-tile (16KB)
// staged in dynamic smem.
// ---------------------------------------------------------------------------
__global__ void gemm_kernel(const float* __restrict__ x,
                            const float* __restrict__ W,
                            const float* __restrict__ b,
                            float* __restrict__ sup, int N) {
    extern __shared__ float smem[];
    float* sW = smem;               // 128*128 floats
    float* sx = smem + D * D;       // GEMM_ROWS*128 floats

    const int tid = threadIdx.x;
    const int tx = tid & 31;        // col group (float4)
    const int ty = tid >> 5;        // warp id 0..7

    // Stage W (vectorized)
    const float4* Wv = (const float4*)W;
    float4* sWv = (float4*)sW;
    #pragma unroll
    for (int i = tid; i < (D * D) / 4; i += 256) sWv[i] = Wv[i];

    // Stage x tile
    const int row0 = blockIdx.x * GEMM_ROWS;
    const float4* xv = (const float4*)(x + (size_t)row0 * D);
    float4* sxv = (float4*)sx;
    #pragma unroll
    for (int i = tid; i < (GEMM_ROWS * D) / 4; i += 256) {
        // guard tail (N may not be multiple of GEMM_ROWS in general)
        int r = (i * 4) / D;
        if (row0 + r < N) sxv[i] = xv[i];
    }
    __syncthreads();

    float4 bv = ((const float4*)b)[tx];
    float4 acc0 = bv, acc1 = bv, acc2 = bv, acc3 = bv;

    const int r0 = ty * 4;          // local rows r0..r0+3
    const float* sx0 = sx + (r0 + 0) * D;
    const float* sx1 = sx + (r0 + 1) * D;
    const float* sx2 = sx + (r0 + 2) * D;
    const float* sx3 = sx + (r0 + 3) * D;
    const float4* sWrow = (const float4*)sW;

    #pragma unroll 8
    for (int k = 0; k < D; k++) {
        float4 wv = sWrow[k * 32 + tx];
        float a0 = sx0[k], a1 = sx1[k], a2 = sx2[k], a3 = sx3[k];
        acc0.x += a0 * wv.x; acc0.y += a0 * wv.y; acc0.z += a0 * wv.z; acc0.w += a0 * wv.w;
        acc1.x += a1 * wv.x; acc1.y += a1 * wv.y; acc1.z += a1 * wv.z; acc1.w += a1 * wv.w;
        acc2.x += a2 * wv.x; acc2.y += a2 * wv.y; acc2.z += a2 * wv.z; acc2.w += a2 * wv.w;
        acc3.x += a3 * wv.x; acc3.y += a3 * wv.y; acc3.z += a3 * wv.z; acc3.w += a3 * wv.w;
    }

    float4* supv = (float4*)sup;
    int gr = row0 + r0;
    if (gr + 0 < N) supv[(size_t)(gr + 0) * 32 + tx] = acc0;
    if (gr + 1 < N) supv[(size_t)(gr + 1) * 32 + tx] = acc1;
    if (gr + 2 < N) supv[(size_t)(gr + 2) * 32 + tx] = acc2;
    if (gr + 3 < N) supv[(size_t)(gr + 3) * 32 + tx] = acc3;
}

// ---------------------------------------------------------------------------
// Kernel 2: out[dst] += w_e * support[src]   (edge_dst sorted -> run-accumulate
// in registers, atomicAdd only at run boundaries)
// Block: 128 threads = 4 chains x 32 lanes. Each chain walks EPB/4 consecutive
// edges; each lane owns one float4 of the 128 features. Next-edge prefetch.
// ---------------------------------------------------------------------------
__global__ void scatter_kernel(const float* __restrict__ sup,
                               const float* __restrict__ ew,
                               const int* __restrict__ esrc,
                               const int* __restrict__ edst,
                               float* __restrict__ out, int E) {
    __shared__ int   s_src[EPB];
    __shared__ int   s_dst[EPB];
    __shared__ float s_w[EPB];

    const int base = blockIdx.x * EPB;
    const int n = min(EPB, E - base);

    for (int i = threadIdx.x; i < n; i += blockDim.x) {
        s_src[i] = esrc[base + i];
        s_dst[i] = edst[base + i];
        s_w[i]   = ew[base + i];
    }
    __syncthreads();

    const int chain = threadIdx.x >> 5;
    const int lane  = threadIdx.x & 31;
    const int cbeg  = chain * (EPB / CHAINS);
    const int cend  = min(cbeg + EPB / CHAINS, n);
    if (cbeg >= cend) return;

    const float4* supv = (const float4*)sup;

    float4 acc = make_float4(0.f, 0.f, 0.f, 0.f);
    float4 v = supv[(size_t)s_src[cbeg] * 32 + lane];
    float  w = s_w[cbeg];

    for (int e = cbeg; e < cend; e++) {
        // prefetch next edge's row (independent load -> MLP=2)
        float4 vn = make_float4(0.f, 0.f, 0.f, 0.f);
        float  wn = 0.f;
        if (e + 1 < cend) {
            vn = supv[(size_t)s_src[e + 1] * 32 + lane];
            wn = s_w[e + 1];
        }

        acc.x += w * v.x; acc.y += w * v.y; acc.z += w * v.z; acc.w += w * v.w;

        bool flush = (e + 1 == cend) || (s_dst[e + 1] != s_dst[e]);
        if (flush) {
            float* o = out + (size_t)s_dst[e] * D + lane * 4;
            atomicAdd(o + 0, acc.x);
            atomicAdd(o + 1, acc.y);
            atomicAdd(o + 2, acc.z);
            atomicAdd(o + 3, acc.w);
            acc = make_float4(0.f, 0.f, 0.f, 0.f);
        }
        v = vn; w = wn;
    }
}

extern "C" void kernel_launch(void* const* d_in, const int* in_sizes, int n_in,
                              void* d_out, int out_size) {
    const float* x    = (const float*)d_in[0];
    const float* W    = (const float*)d_in[1];
    const float* b    = (const float*)d_in[2];
    const float* ew   = (const float*)d_in[3];
    const int*   esrc = (const int*)d_in[4];
    const int*   edst = (const int*)d_in[5];
    float* out = (float*)d_out;

    const int N = in_sizes[0] / D;
    const int E = in_sizes[3];

    float* sup = nullptr;
    cudaGetSymbolAddress((void**)&sup, g_support);

    // GEMM: 80KB dynamic smem (W 64KB + x tile 16KB)
    const int gemm_smem = (D * D + GEMM_ROWS * D) * (int)sizeof(float);
    cudaFuncSetAttribute(gemm_kernel, cudaFuncAttributeMaxDynamicSharedMemorySize, gemm_smem);

    const int gemm_blocks = (N + GEMM_ROWS - 1) / GEMM_ROWS;
    gemm_kernel<<<gemm_blocks, 256, gemm_smem>>>(x, W, b, sup, N);

    cudaMemsetAsync(d_out, 0, (size_t)out_size * sizeof(float));

    const int scat_blocks = (E + EPB - 1) / EPB;
    scatter_kernel<<<scat_blocks, 128>>>(sup, ew, esrc, edst, out, E);
}

// round 2
// speedup vs baseline: 1.2143x; 1.2143x over previous
#include <cuda_runtime.h>
#include <cuda_fp16.h>

#define D 128
#define MAX_N 100000
#define MBLK 64            // rows of x per GEMM block
#define PADX 132           // x smem row stride (floats): 132 mod 32 = 4 -> A frag conflict-free
#define PADW 136           // W smem row stride (floats): 136 mod 32 = 8 -> B frag conflict-free
#define EPB 256            // edges per scatter block
#define CHAINS 4

// support = x@W + b, stored fp16 (25.6 MB)
__device__ __half g_support_h[(size_t)MAX_N * D];

__device__ __forceinline__ unsigned f2tf32(float f) {
    unsigned r;
    asm("cvt.rna.tf32.f32 %0, %1;" : "=r"(r) : "f"(f));
    return r;
}

__device__ __forceinline__ void mma_tf32(float d[4], const unsigned a[4],
                                         unsigned b0, unsigned b1) {
    asm volatile(
        "mma.sync.aligned.m16n8k8.row.col.f32.tf32.tf32.f32 "
        "{%0,%1,%2,%3}, {%4,%5,%6,%7}, {%8,%9}, {%0,%1,%2,%3};"
        : "+f"(d[0]), "+f"(d[1]), "+f"(d[2]), "+f"(d[3])
        : "r"(a[0]), "r"(a[1]), "r"(a[2]), "r"(a[3]), "r"(b0), "r"(b1));
}

// ---------------------------------------------------------------------------
// GEMM: support[n][:] = x[n][:] @ W + b   via tf32 mma with 2-term x split.
// Block 256 threads = 8 warps in 4(m) x 2(n) grid. Warp tile: 16 rows x 64 cols.
// ---------------------------------------------------------------------------
__global__ void gemm_mma_kernel(const float* __restrict__ x,
                                const float* __restrict__ W,
                                const float* __restrict__ b,
                                __half* __restrict__ sup, int N) {
    extern __shared__ float smem[];
    float* sX = smem;                    // 64 x PADX
    float* sW = smem + MBLK * PADX;      // 128 x PADW

    const int tid  = threadIdx.x;
    const int lane = tid & 31;
    const int w    = tid >> 5;
    const int wm   = w & 3;              // 0..3 -> 16-row chunk
    const int wn   = w >> 2;             // 0..1 -> 64-col chunk
    const int g    = lane >> 2;          // groupID 0..7
    const int tig  = lane & 3;           // 0..3

    const int row0 = blockIdx.x * MBLK;

    // Stage W: 128 x 128 floats (32 float4-cols)
    const float4* Wv = (const float4*)W;
    for (int i = tid; i < 128 * 32; i += 256) {
        int r = i >> 5, c = i & 31;
        *(float4*)(sW + r * PADW + c * 4) = Wv[i];
    }
    // Stage x tile: 64 x 128 floats
    const float4* xv = (const float4*)x;
    for (int i = tid; i < MBLK * 32; i += 256) {
        int r = i >> 5, c = i & 31;
        float4 v = make_float4(0.f, 0.f, 0.f, 0.f);
        if (row0 + r < N) v = xv[(size_t)(row0 + r) * 32 + c];
        *(float4*)(sX + r * PADX + c * 4) = v;
    }
    __syncthreads();

    float acc[8][4];
    #pragma unroll
    for (int t = 0; t < 8; t++)
        #pragma unroll
        for (int j = 0; j < 4; j++) acc[t][j] = 0.f;

    const int ar0 = wm * 16 + g;         // local A rows
    const int ar1 = ar0 + 8;

    #pragma unroll
    for (int k0 = 0; k0 < D; k0 += 8) {
        // A fragment (fp32), then split into tf32 hi + lo
        float fa[4];
        fa[0] = sX[ar0 * PADX + k0 + tig];
        fa[1] = sX[ar1 * PADX + k0 + tig];
        fa[2] = sX[ar0 * PADX + k0 + tig + 4];
        fa[3] = sX[ar1 * PADX + k0 + tig + 4];
        unsigned ah[4], al[4];
        #pragma unroll
        for (int j = 0; j < 4; j++) {
            ah[j] = f2tf32(fa[j]);
            al[j] = f2tf32(fa[j] - __uint_as_float(ah[j]));
        }
        #pragma unroll
        for (int t = 0; t < 8; t++) {
            int n0 = wn * 64 + t * 8;
            unsigned b0 = f2tf32(sW[(k0 + tig) * PADW + n0 + g]);
            unsigned b1 = f2tf32(sW[(k0 + tig + 4) * PADW + n0 + g]);
            mma_tf32(acc[t], ah, b0, b1);
            mma_tf32(acc[t], al, b0, b1);
        }
    }

    // Epilogue: add bias, convert to fp16, store
    const int gr0 = row0 + wm * 16 + g;
    const int gr1 = gr0 + 8;
    #pragma unroll
    for (int t = 0; t < 8; t++) {
        int col = wn * 64 + t * 8 + 2 * tig;
        float bx = b[col], by = b[col + 1];
        if (gr0 < N) {
            __half2 h = __floats2half2_rn(acc[t][0] + bx, acc[t][1] + by);
            *(__half2*)(sup + (size_t)gr0 * D + col) = h;
        }
        if (gr1 < N) {
            __half2 h = __floats2half2_rn(acc[t][2] + bx, acc[t][3] + by);
            *(__half2*)(sup + (size_t)gr1 * D + col) = h;
        }
    }
}

// ---------------------------------------------------------------------------
// Scatter: out[dst] += w_e * support[src]  (fp16 gather, fp32 accumulate).
// edge_dst sorted -> run-accumulate in registers, atomics only at boundaries.
// Block 128 threads = 4 chains x 32 lanes; lane owns 4 features (8B fp16).
// ---------------------------------------------------------------------------
__global__ void scatter_kernel(const __half* __restrict__ sup,
                               const float* __restrict__ ew,
                               const int* __restrict__ esrc,
                               const int* __restrict__ edst,
                               float* __restrict__ out, int E) {
    __shared__ int   s_src[EPB];
    __shared__ int   s_dst[EPB];
    __shared__ float s_w[EPB];

    const int base = blockIdx.x * EPB;
    const int n = min(EPB, E - base);

    for (int i = threadIdx.x; i < n; i += blockDim.x) {
        s_src[i] = esrc[base + i];
        s_dst[i] = edst[base + i];
        s_w[i]   = ew[base + i];
    }
    __syncthreads();

    const int chain = threadIdx.x >> 5;
    const int lane  = threadIdx.x & 31;
    const int cbeg  = chain * (EPB / CHAINS);
    const int cend  = min(cbeg + EPB / CHAINS, n);
    if (cbeg >= cend) return;

    const uint2* supv = (const uint2*)sup;   // 128 halves = 32 uint2 per row

    float4 acc = make_float4(0.f, 0.f, 0.f, 0.f);
    uint2 u = supv[(size_t)s_src[cbeg] * 32 + lane];
    float w = s_w[cbeg];

    for (int e = cbeg; e < cend; e++) {
        uint2 un = make_uint2(0u, 0u);
        float wn = 0.f;
        if (e + 1 < cend) {
            un = supv[(size_t)s_src[e + 1] * 32 + lane];
            wn = s_w[e + 1];
        }

        float2 f0 = __half22float2(*(__half2*)(&u.x));
        float2 f1 = __half22float2(*(__half2*)(&u.y));
        acc.x += w * f0.x; acc.y += w * f0.y;
        acc.z += w * f1.x; acc.w += w * f1.y;

        bool flush = (e + 1 == cend) || (s_dst[e + 1] != s_dst[e]);
        if (flush) {
            float* o = out + (size_t)s_dst[e] * D + lane * 4;
            atomicAdd(o + 0, acc.x);
            atomicAdd(o + 1, acc.y);
            atomicAdd(o + 2, acc.z);
            atomicAdd(o + 3, acc.w);
            acc = make_float4(0.f, 0.f, 0.f, 0.f);
        }
        u = un; w = wn;
    }
}

extern "C" void kernel_launch(void* const* d_in, const int* in_sizes, int n_in,
                              void* d_out, int out_size) {
    const float* x    = (const float*)d_in[0];
    const float* W    = (const float*)d_in[1];
    const float* b    = (const float*)d_in[2];
    const float* ew   = (const float*)d_in[3];
    const int*   esrc = (const int*)d_in[4];
    const int*   edst = (const int*)d_in[5];
    float* out = (float*)d_out;

    const int N = in_sizes[0] / D;
    const int E = in_sizes[3];

    __half* sup = nullptr;
    cudaGetSymbolAddress((void**)&sup, g_support_h);

    const int gemm_smem = (MBLK * PADX + D * PADW) * (int)sizeof(float); // ~103 KB
    cudaFuncSetAttribute(gemm_mma_kernel, cudaFuncAttributeMaxDynamicSharedMemorySize, gemm_smem);

    const int gemm_blocks = (N + MBLK - 1) / MBLK;
    gemm_mma_kernel<<<gemm_blocks, 256, gemm_smem>>>(x, W, b, sup, N);

    cudaMemsetAsync(d_out, 0, (size_t)out_size * sizeof(float));

    const int scat_blocks = (E + EPB - 1) / EPB;
    scatter_kernel<<<scat_blocks, 128>>>(sup, ew, esrc, edst, out, E);
}

// round 3
// speedup vs baseline: 1.4488x; 1.1932x over previous
#include <cuda_runtime.h>
#include <cuda_fp16.h>

#define D 128
#define MAX_N 100000
#define MBLK 64            // rows of x per GEMM block
#define PADX 132           // x smem row stride: 132 mod 32 = 4 -> A frag conflict-free
#define PADW 136           // W smem row stride: 136 mod 32 = 8 -> B frag conflict-free
#define EPB 256            // edges per scatter block

// support = x@W + b, stored fp16 (25.6 MB)
__device__ __half g_support_h[(size_t)MAX_N * D];
// W pre-rounded to tf32 (stored as float bits)
__device__ float g_Wt[D * D];

__device__ __forceinline__ float f2tf32f(float f) {
    unsigned r;
    asm("cvt.rna.tf32.f32 %0, %1;" : "=r"(r) : "f"(f));
    return __uint_as_float(r);
}

__device__ __forceinline__ void mma_tf32(float d[4], const float a[4],
                                         float b0, float b1) {
    asm volatile(
        "mma.sync.aligned.m16n8k8.row.col.f32.tf32.tf32.f32 "
        "{%0,%1,%2,%3}, {%4,%5,%6,%7}, {%8,%9}, {%0,%1,%2,%3};"
        : "+f"(d[0]), "+f"(d[1]), "+f"(d[2]), "+f"(d[3])
        : "r"(__float_as_uint(a[0])), "r"(__float_as_uint(a[1])),
          "r"(__float_as_uint(a[2])), "r"(__float_as_uint(a[3])),
          "r"(__float_as_uint(b0)), "r"(__float_as_uint(b1)));
}

// Pre-round W to tf32 once (16K elements)
__global__ void prep_kernel(const float* __restrict__ W, float* __restrict__ Wt) {
    int i = blockIdx.x * blockDim.x + threadIdx.x;
    if (i < D * D) Wt[i] = f2tf32f(W[i]);
}

// ---------------------------------------------------------------------------
// GEMM: support = x@W + b via tf32 mma, 2-term split of x (hi+lo), W pre-tf32.
// All cvts happen at staging; mainloop is pure LDS + HMMA.
// Block 256 = 8 warps in 4(m) x 2(n). Warp tile 16 x 64.
// ---------------------------------------------------------------------------
__global__ void gemm_mma_kernel(const float* __restrict__ x,
                                const float* __restrict__ Wt,
                                const float* __restrict__ b,
                                __half* __restrict__ sup, int N) {
    extern __shared__ float smem[];
    float* sXh = smem;                       // 64 x PADX
    float* sXl = smem + MBLK * PADX;         // 64 x PADX
    float* sW  = smem + 2 * MBLK * PADX;     // 128 x PADW

    const int tid  = threadIdx.x;
    const int lane = tid & 31;
    const int w    = tid >> 5;
    const int wm   = w & 3;
    const int wn   = w >> 2;
    const int g    = lane >> 2;
    const int tig  = lane & 3;

    const int row0 = blockIdx.x * MBLK;

    // Stage W (already tf32-rounded, plain copy)
    const float4* Wv = (const float4*)Wt;
    #pragma unroll
    for (int i = tid; i < 128 * 32; i += 256) {
        int r = i >> 5, c = i & 31;
        *(float4*)(sW + r * PADW + c * 4) = Wv[i];
    }
    // Stage x, split hi/lo tf32 at staging time (each element converted once)
    const float4* xv = (const float4*)x;
    #pragma unroll
    for (int i = tid; i < MBLK * 32; i += 256) {
        int r = i >> 5, c = i & 31;
        float4 v = make_float4(0.f, 0.f, 0.f, 0.f);
        if (row0 + r < N) v = xv[(size_t)(row0 + r) * 32 + c];
        float4 h, l;
        h.x = f2tf32f(v.x); l.x = f2tf32f(v.x - h.x);
        h.y = f2tf32f(v.y); l.y = f2tf32f(v.y - h.y);
        h.z = f2tf32f(v.z); l.z = f2tf32f(v.z - h.z);
        h.w = f2tf32f(v.w); l.w = f2tf32f(v.w - h.w);
        *(float4*)(sXh + r * PADX + c * 4) = h;
        *(float4*)(sXl + r * PADX + c * 4) = l;
    }
    __syncthreads();

    float acc[8][4];
    #pragma unroll
    for (int t = 0; t < 8; t++)
        #pragma unroll
        for (int j = 0; j < 4; j++) acc[t][j] = 0.f;

    const int ar0 = wm * 16 + g;
    const int ar1 = ar0 + 8;

    #pragma unroll
    for (int k0 = 0; k0 < D; k0 += 8) {
        float ah[4], al[4];
        ah[0] = sXh[ar0 * PADX + k0 + tig];
        ah[1] = sXh[ar1 * PADX + k0 + tig];
        ah[2] = sXh[ar0 * PADX + k0 + tig + 4];
        ah[3] = sXh[ar1 * PADX + k0 + tig + 4];
        al[0] = sXl[ar0 * PADX + k0 + tig];
        al[1] = sXl[ar1 * PADX + k0 + tig];
        al[2] = sXl[ar0 * PADX + k0 + tig + 4];
        al[3] = sXl[ar1 * PADX + k0 + tig + 4];
        #pragma unroll
        for (int t = 0; t < 8; t++) {
            int n0 = wn * 64 + t * 8;
            float b0 = sW[(k0 + tig) * PADW + n0 + g];
            float b1 = sW[(k0 + tig + 4) * PADW + n0 + g];
            mma_tf32(acc[t], ah, b0, b1);
            mma_tf32(acc[t], al, b0, b1);
        }
    }

    // Epilogue: add bias, convert to fp16, store
    const int gr0 = row0 + wm * 16 + g;
    const int gr1 = gr0 + 8;
    #pragma unroll
    for (int t = 0; t < 8; t++) {
        int col = wn * 64 + t * 8 + 2 * tig;
        float bx = b[col], by = b[col + 1];
        if (gr0 < N) {
            __half2 h = __floats2half2_rn(acc[t][0] + bx, acc[t][1] + by);
            *(__half2*)(sup + (size_t)gr0 * D + col) = h;
        }
        if (gr1 < N) {
            __half2 h = __floats2half2_rn(acc[t][2] + bx, acc[t][3] + by);
            *(__half2*)(sup + (size_t)gr1 * D + col) = h;
        }
    }
}

// ---------------------------------------------------------------------------
// Scatter: out[dst] += w_e * support[src]  (fp16 gather, fp32 accumulate).
// Sentinel-padded metadata: no bounds checks in the hot loop. (src,dst) packed
// in int2 -> single LDS.64. Uniform flush branch (dst compare is warp-uniform).
// Block 128 threads = 4 chains x 32 lanes; chain = 64 consecutive edges.
// ---------------------------------------------------------------------------
__global__ void __launch_bounds__(128) scatter_kernel(
        const __half* __restrict__ sup,
        const float* __restrict__ ew,
        const int* __restrict__ esrc,
        const int* __restrict__ edst,
        float* __restrict__ out, int E) {
    __shared__ int2  s_sd[EPB + 1];
    __shared__ float s_w[EPB + 1];

    const int base = blockIdx.x * EPB;
    const int n = min(EPB, E - base);

    for (int i = threadIdx.x; i < n; i += 128) {
        s_sd[i] = make_int2(esrc[base + i], edst[base + i]);
        s_w[i]  = ew[base + i];
    }
    __syncthreads();
    // Sentinels: same (valid) src/dst as last real edge, weight 0.
    for (int i = n + (int)threadIdx.x; i <= EPB; i += 128) {
        s_sd[i] = s_sd[n - 1];
        s_w[i]  = 0.f;
    }
    __syncthreads();

    const int chain = threadIdx.x >> 5;
    const int lane  = threadIdx.x & 31;
    const int cbeg  = chain * (EPB / 4);

    const uint2* supv = (const uint2*)sup;

    int2  sd = s_sd[cbeg];
    float w  = s_w[cbeg];
    uint2 u  = supv[sd.x * 32 + lane];

    float4 acc = make_float4(0.f, 0.f, 0.f, 0.f);

    #pragma unroll 8
    for (int j = 0; j < EPB / 4; j++) {
        const int e = cbeg + j;
        // prefetch next edge (sentinel-padded: always safe)
        int2  sdn = s_sd[e + 1];
        float wn  = s_w[e + 1];
        uint2 un  = supv[sdn.x * 32 + lane];

        float2 f0 = __half22float2(*(__half2*)(&u.x));
        float2 f1 = __half22float2(*(__half2*)(&u.y));
        acc.x += w * f0.x; acc.y += w * f0.y;
        acc.z += w * f1.x; acc.w += w * f1.y;

        // warp-uniform flush: end of chain or destination changes
        if ((j == EPB / 4 - 1) | (sd.y != sdn.y)) {
            float* o = out + (size_t)sd.y * D + lane * 4;
            atomicAdd(o + 0, acc.x);
            atomicAdd(o + 1, acc.y);
            atomicAdd(o + 2, acc.z);
            atomicAdd(o + 3, acc.w);
            acc = make_float4(0.f, 0.f, 0.f, 0.f);
        }
        sd = sdn; w = wn; u = un;
    }
}

extern "C" void kernel_launch(void* const* d_in, const int* in_sizes, int n_in,
                              void* d_out, int out_size) {
    const float* x    = (const float*)d_in[0];
    const float* W    = (const float*)d_in[1];
    const float* b    = (const float*)d_in[2];
    const float* ew   = (const float*)d_in[3];
    const int*   esrc = (const int*)d_in[4];
    const int*   edst = (const int*)d_in[5];
    float* out = (float*)d_out;

    const int N = in_sizes[0] / D;
    const int E = in_sizes[3];

    __half* sup = nullptr;
    cudaGetSymbolAddress((void**)&sup, g_support_h);
    float* Wt = nullptr;
    cudaGetSymbolAddress((void**)&Wt, g_Wt);

    prep_kernel<<<(D * D + 255) / 256, 256>>>(W, Wt);

    const int gemm_smem = (2 * MBLK * PADX + D * PADW) * (int)sizeof(float); // ~134 KB
    cudaFuncSetAttribute(gemm_mma_kernel, cudaFuncAttributeMaxDynamicSharedMemorySize, gemm_smem);

    const int gemm_blocks = (N + MBLK - 1) / MBLK;
    gemm_mma_kernel<<<gemm_blocks, 256, gemm_smem>>>(x, Wt, b, sup, N);

    cudaMemsetAsync(d_out, 0, (size_t)out_size * sizeof(float));

    const int scat_blocks = (E + EPB - 1) / EPB;
    scatter_kernel<<<scat_blocks, 128>>>(sup, ew, esrc, edst, out, E);
}

// round 4
// speedup vs baseline: 2.1285x; 1.4691x over previous
#include <cuda_runtime.h>
#include <cuda_fp16.h>

#define D 128
#define MAX_N 100000
#define MBLK 64            // rows of x per GEMM block
#define PADH 136           // smem row stride in halves: word stride 68 -> (4r+tig) mod 32 distinct
#define EPB 512            // edges per scatter block

// support = x@W + b, stored fp16 (25.6 MB)
__device__ __half g_support_h[(size_t)MAX_N * D];
// W transposed + converted to fp16: Wt[n][k]
__device__ __half g_Wt_h[D * D];

// ---------------------------------------------------------------------------
// prep: Wt_h[n][k] = fp16(W[k][n])   (16K elements, trivial)
// ---------------------------------------------------------------------------
__global__ void prep_kernel(const float* __restrict__ W, __half* __restrict__ Wt) {
    int i = blockIdx.x * blockDim.x + threadIdx.x;
    if (i < D * D) {
        int k = i >> 7, n = i & 127;
        Wt[n * D + k] = __float2half(W[i]);
    }
}

__device__ __forceinline__ void mma_f16(float d[4], unsigned a0, unsigned a1,
                                        unsigned a2, unsigned a3,
                                        unsigned b0, unsigned b1) {
    asm volatile(
        "mma.sync.aligned.m16n8k16.row.col.f32.f16.f16.f32 "
        "{%0,%1,%2,%3}, {%4,%5,%6,%7}, {%8,%9}, {%0,%1,%2,%3};"
        : "+f"(d[0]), "+f"(d[1]), "+f"(d[2]), "+f"(d[3])
        : "r"(a0), "r"(a1), "r"(a2), "r"(a3), "r"(b0), "r"(b1));
}

// ---------------------------------------------------------------------------
// GEMM: support = fp16(x@W + b) via fp16 mma m16n8k16.
// Block 256 = 8 warps in 4(m) x 2(n); warp tile 16 x 64. Also zeroes its
// 64 rows of `out` (replaces the memset; stores overlap tensor work).
// ---------------------------------------------------------------------------
__global__ void __launch_bounds__(256) gemm_mma_kernel(
        const float* __restrict__ x,
        const __half* __restrict__ Wt,
        const float* __restrict__ b,
        __half* __restrict__ sup,
        float* __restrict__ out, int N) {
    extern __shared__ __half smem[];
    __half* sX = smem;                 // 64  x PADH halves
    __half* sW = smem + MBLK * PADH;   // 128 x PADH halves ([n][k])

    const int tid  = threadIdx.x;
    const int lane = tid & 31;
    const int w    = tid >> 5;
    const int wm   = w & 3;
    const int wn   = w >> 2;
    const int g    = lane >> 2;
    const int tig  = lane & 3;

    const int row0 = blockIdx.x * MBLK;

    // Stage Wt (fp16, already transposed): 128 rows x 16 uint4
    const uint4* Wv = (const uint4*)Wt;
    #pragma unroll
    for (int i = tid; i < 128 * 16; i += 256) {
        int r = i >> 4, c = i & 15;
        *(uint4*)(sW + r * PADH + c * 8) = Wv[i];
    }
    // Stage x (fp32 -> fp16): 64 rows x 32 float4 -> uint2 halves
    const float4* xv = (const float4*)x;
    #pragma unroll
    for (int i = tid; i < MBLK * 32; i += 256) {
        int r = i >> 5, c = i & 31;
        float4 v = make_float4(0.f, 0.f, 0.f, 0.f);
        if (row0 + r < N) v = xv[(size_t)(row0 + r) * 32 + c];
        __half2 h0 = __floats2half2_rn(v.x, v.y);
        __half2 h1 = __floats2half2_rn(v.z, v.w);
        uint2 p = make_uint2(*(unsigned*)&h0, *(unsigned*)&h1);
        *(uint2*)(sX + r * PADH + c * 4) = p;
    }
    __syncthreads();

    float acc[8][4];
    #pragma unroll
    for (int t = 0; t < 8; t++)
        #pragma unroll
        for (int j = 0; j < 4; j++) acc[t][j] = 0.f;

    const int ar0 = wm * 16 + g;
    const int ar1 = ar0 + 8;

    #pragma unroll
    for (int k0 = 0; k0 < D; k0 += 16) {
        unsigned a0 = *(const unsigned*)(sX + ar0 * PADH + k0 + 2 * tig);
        unsigned a1 = *(const unsigned*)(sX + ar1 * PADH + k0 + 2 * tig);
        unsigned a2 = *(const unsigned*)(sX + ar0 * PADH + k0 + 2 * tig + 8);
        unsigned a3 = *(const unsigned*)(sX + ar1 * PADH + k0 + 2 * tig + 8);
        #pragma unroll
        for (int t = 0; t < 8; t++) {
            int n0 = wn * 64 + t * 8;
            unsigned b0 = *(const unsigned*)(sW + (n0 + g) * PADH + k0 + 2 * tig);
            unsigned b1 = *(const unsigned*)(sW + (n0 + g) * PADH + k0 + 2 * tig + 8);
            mma_f16(acc[t], a0, a1, a2, a3, b0, b1);
        }
    }

    // Epilogue: bias + fp16 store of support
    const int gr0 = row0 + wm * 16 + g;
    const int gr1 = gr0 + 8;
    #pragma unroll
    for (int t = 0; t < 8; t++) {
        int col = wn * 64 + t * 8 + 2 * tig;
        float bx = b[col], by = b[col + 1];
        if (gr0 < N) {
            __half2 h = __floats2half2_rn(acc[t][0] + bx, acc[t][1] + by);
            *(__half2*)(sup + (size_t)gr0 * D + col) = h;
        }
        if (gr1 < N) {
            __half2 h = __floats2half2_rn(acc[t][2] + bx, acc[t][3] + by);
            *(__half2*)(sup + (size_t)gr1 * D + col) = h;
        }
    }

    // Zero this block's rows of out (replaces global memset)
    const float4 z4 = make_float4(0.f, 0.f, 0.f, 0.f);
    float4* outv = (float4*)out;
    #pragma unroll
    for (int i = tid; i < MBLK * 32; i += 256) {
        int r = i >> 5;
        if (row0 + r < N) outv[(size_t)(row0 + r) * 32 + (i & 31)] = z4;
    }
}

// ---------------------------------------------------------------------------
// Scatter: out[dst] += w_e * support[src]  (fp16 gather, fp32 accumulate).
// Sentinel-padded, int2-packed metadata, run-accumulate with uniform flush.
// Block 128 threads = 4 chains x 128 edges.
// ---------------------------------------------------------------------------
__global__ void __launch_bounds__(128) scatter_kernel(
        const __half* __restrict__ sup,
        const float* __restrict__ ew,
        const int* __restrict__ esrc,
        const int* __restrict__ edst,
        float* __restrict__ out, int E) {
    __shared__ int2  s_sd[EPB + 1];
    __shared__ float s_w[EPB + 1];

    const int base = blockIdx.x * EPB;
    const int n = min(EPB, E - base);

    for (int i = threadIdx.x; i < n; i += 128) {
        s_sd[i] = make_int2(esrc[base + i], edst[base + i]);
        s_w[i]  = ew[base + i];
    }
    __syncthreads();
    for (int i = n + (int)threadIdx.x; i <= EPB; i += 128) {
        s_sd[i] = s_sd[n - 1];
        s_w[i]  = 0.f;
    }
    __syncthreads();

    const int chain = threadIdx.x >> 5;
    const int lane  = threadIdx.x & 31;
    const int cbeg  = chain * (EPB / 4);

    const uint2* supv = (const uint2*)sup;

    int2  sd = s_sd[cbeg];
    float w  = s_w[cbeg];
    uint2 u  = supv[sd.x * 32 + lane];

    float4 acc = make_float4(0.f, 0.f, 0.f, 0.f);

    #pragma unroll 8
    for (int j = 0; j < EPB / 4; j++) {
        const int e = cbeg + j;
        int2  sdn = s_sd[e + 1];
        float wn  = s_w[e + 1];
        uint2 un  = supv[sdn.x * 32 + lane];

        float2 f0 = __half22float2(*(__half2*)(&u.x));
        float2 f1 = __half22float2(*(__half2*)(&u.y));
        acc.x += w * f0.x; acc.y += w * f0.y;
        acc.z += w * f1.x; acc.w += w * f1.y;

        if ((j == EPB / 4 - 1) | (sd.y != sdn.y)) {
            float* o = out + (size_t)sd.y * D + lane * 4;
            atomicAdd(o + 0, acc.x);
            atomicAdd(o + 1, acc.y);
            atomicAdd(o + 2, acc.z);
            atomicAdd(o + 3, acc.w);
            acc = make_float4(0.f, 0.f, 0.f, 0.f);
        }
        sd = sdn; w = wn; u = un;
    }
}

extern "C" void kernel_launch(void* const* d_in, const int* in_sizes, int n_in,
                              void* d_out, int out_size) {
    const float* x    = (const float*)d_in[0];
    const float* W    = (const float*)d_in[1];
    const float* b    = (const float*)d_in[2];
    const float* ew   = (const float*)d_in[3];
    const int*   esrc = (const int*)d_in[4];
    const int*   edst = (const int*)d_in[5];
    float* out = (float*)d_out;

    const int N = in_sizes[0] / D;
    const int E = in_sizes[3];

    __half* sup = nullptr;
    cudaGetSymbolAddress((void**)&sup, g_support_h);
    __half* Wt = nullptr;
    cudaGetSymbolAddress((void**)&Wt, g_Wt_h);

    prep_kernel<<<(D * D + 255) / 256, 256>>>(W, Wt);

    const int gemm_smem = (MBLK * PADH + D * PADH) * (int)sizeof(__half); // ~52 KB
    cudaFuncSetAttribute(gemm_mma_kernel, cudaFuncAttributeMaxDynamicSharedMemorySize, gemm_smem);

    const int gemm_blocks = (N + MBLK - 1) / MBLK;
    gemm_mma_kernel<<<gemm_blocks, 256, gemm_smem>>>(x, Wt, b, sup, out, N);

    const int scat_blocks = (E + EPB - 1) / EPB;
    scatter_kernel<<<scat_blocks, 128>>>(sup, ew, esrc, edst, out, E);
}